// round 15
// baseline (speedup 1.0000x reference)
#include <cuda_runtime.h>
#include <cuda_bf16.h>
#include <cstdint>
#include <cstddef>
#include <math.h>

#define NN   50000
#define EE   800000
#define FIN  512
#define D1   128      // HEADS * FPH
#define H1   8
#define C2   32       // NUM_CLASSES
#define NEG  0.2f
#define MNEG (-3.0e38f)

// ---------------- scratch (device globals; no allocation allowed) ----------
__device__ float g_h1 [NN * D1];   // x @ W1
__device__ float g_as1[NN * H1];
__device__ float g_ad1[NN * H1];
__device__ float g_h2 [NN * C2];   // elu(agg1)+b1 @ W2
__device__ float g_as2[NN];
__device__ float g_ad2[NN];
__device__ int   g_off [NN + 1];   // CSR offsets by dst
__device__ int   g_cur [NN];       // scatter cursors
__device__ int   g_ssrc[EE];       // src ids sorted by dst segment
__device__ __nv_bfloat16 g_w1t_hi[D1 * FIN];   // W1^T hi  [128 n][512 k]
__device__ __nv_bfloat16 g_w1t_lo[D1 * FIN];   // W1^T lo

// ===== pre: W1T hi/lo split (blocks 0..255) + zero offsets (blocks 256+) ===
__global__ void k_pre(const float* __restrict__ W1) {
    if (blockIdx.x < 256) {
        int i = blockIdx.x * 256 + threadIdx.x;      // FIN*D1 = 65536 exactly
        int k = i >> 7, n = i & 127;
        float w = W1[i];
        __nv_bfloat16 hi = __float2bfloat16_rn(w);
        __nv_bfloat16 lo = __float2bfloat16_rn(w - __bfloat162float(hi));
        g_w1t_hi[n * FIN + k] = hi;
        g_w1t_lo[n * FIN + k] = lo;
    } else {
        int i = (blockIdx.x - 256) * 256 + threadIdx.x;
        if (i <= NN) g_off[i] = 0;
    }
}

// ============ mma.sync + cp.async + ldmatrix helpers =======================
__device__ __forceinline__ void mma16816(float* c, const uint32_t* a, const uint32_t* b) {
    asm volatile(
        "mma.sync.aligned.m16n8k16.row.col.f32.bf16.bf16.f32 "
        "{%0,%1,%2,%3}, {%4,%5,%6,%7}, {%8,%9}, {%0,%1,%2,%3};"
        : "+f"(c[0]), "+f"(c[1]), "+f"(c[2]), "+f"(c[3])
        : "r"(a[0]), "r"(a[1]), "r"(a[2]), "r"(a[3]), "r"(b[0]), "r"(b[1]));
}
__device__ __forceinline__ void cp_async16(void* dst, const void* src, int srcbytes) {
    uint32_t d = (uint32_t)__cvta_generic_to_shared(dst);
    asm volatile("cp.async.ca.shared.global [%0], [%1], 16, %2;"
                 :: "r"(d), "l"(src), "r"(srcbytes) : "memory");
}
#define CP_COMMIT() asm volatile("cp.async.commit_group;" ::: "memory")
#define CP_WAIT0()  asm volatile("cp.async.wait_group 0;" ::: "memory")
__device__ __forceinline__ void ldsm4(uint32_t* r, uint32_t saddr) {
    asm volatile("ldmatrix.sync.aligned.m8n8.x4.shared.b16 {%0,%1,%2,%3}, [%4];"
                 : "=r"(r[0]), "=r"(r[1]), "=r"(r[2]), "=r"(r[3]) : "r"(saddr));
}

// ====== GEMM1: g_h1 = x @ W1 (bf16x3 split mma.sync) + FUSED attn1 dots ====
#define KC 32
#define LDA 40
#define LDA32 36
#define SM_A32(b)  (sm + (b) * 18432)
#define SM_BHI(b)  (sm + 36864 + (b) * 20480)
#define SM_BLO(b)  (sm + 36864 + (b) * 20480 + 10240)
#define SM_AHI     (sm + 77824)
#define SM_ALO     (sm + 88064)
#define GEMM1_SMEM 98304
__global__ __launch_bounds__(256, 2) void k_gemm1_mma(const float* __restrict__ A,
                                                      const float* __restrict__ att_s,
                                                      const float* __restrict__ att_d) {
    extern __shared__ char sm[];
    const int tid  = threadIdx.x;
    const int bm   = blockIdx.x * 128;
    const int warp = tid >> 5, lane = tid & 31;
    const int g = lane >> 2, tg = lane & 3;
    const int mwarp = warp >> 2, nwarp = warp & 3;
    const int mbase = mwarp * 64;
    const int nbase = nwarp * 32;

    float acc[4][4][4];
#pragma unroll
    for (int mi = 0; mi < 4; mi++)
#pragma unroll
        for (int ni = 0; ni < 4; ni++)
#pragma unroll
            for (int q = 0; q < 4; q++) acc[mi][ni][q] = 0.f;

    auto stage = [&](int k0, int b) {
        float* a32 = reinterpret_cast<float*>(SM_A32(b));
#pragma unroll
        for (int i = 0; i < 4; i++) {
            int idx = i * 256 + tid;
            int r = idx >> 3, q = idx & 7;
            int gr = bm + r;
            int okb = (gr < NN) ? 16 : 0;
            int gc = (gr < NN) ? gr : (NN - 1);
            cp_async16(a32 + r * LDA32 + q * 4,
                       A + (size_t)gc * FIN + k0 + q * 4, okb);
        }
        __nv_bfloat16* bhi = reinterpret_cast<__nv_bfloat16*>(SM_BHI(b));
        __nv_bfloat16* blo = reinterpret_cast<__nv_bfloat16*>(SM_BLO(b));
#pragma unroll
        for (int i = 0; i < 4; i++) {
            int idx = i * 256 + tid;
            int which = idx >> 9, wi = idx & 511;
            int r = wi >> 2, q = wi & 3;
            const __nv_bfloat16* src = (which ? g_w1t_lo : g_w1t_hi) + r * FIN + k0 + q * 8;
            __nv_bfloat16* dst = (which ? blo : bhi) + r * LDA + q * 8;
            cp_async16(dst, src, 16);
        }
        CP_COMMIT();
    };
    auto convert = [&](int b) {
        const float* a32 = reinterpret_cast<const float*>(SM_A32(b));
        __nv_bfloat16* ahi = reinterpret_cast<__nv_bfloat16*>(SM_AHI);
        __nv_bfloat16* alo = reinterpret_cast<__nv_bfloat16*>(SM_ALO);
#pragma unroll
        for (int i = 0; i < 4; i++) {
            int idx = i * 256 + tid;
            int r = idx >> 3, q = idx & 7;
            float4 v = *reinterpret_cast<const float4*>(a32 + r * LDA32 + q * 4);
            __nv_bfloat162 h01 = __floats2bfloat162_rn(v.x, v.y);
            __nv_bfloat162 h23 = __floats2bfloat162_rn(v.z, v.w);
            float l0 = v.x - __bfloat162float(h01.x);
            float l1 = v.y - __bfloat162float(h01.y);
            float l2 = v.z - __bfloat162float(h23.x);
            float l3 = v.w - __bfloat162float(h23.y);
            __nv_bfloat162 p01 = __floats2bfloat162_rn(l0, l1);
            __nv_bfloat162 p23 = __floats2bfloat162_rn(l2, l3);
            int so = r * LDA + q * 4;
            *reinterpret_cast<uint2*>(ahi + so) =
                make_uint2(*reinterpret_cast<uint32_t*>(&h01), *reinterpret_cast<uint32_t*>(&h23));
            *reinterpret_cast<uint2*>(alo + so) =
                make_uint2(*reinterpret_cast<uint32_t*>(&p01), *reinterpret_cast<uint32_t*>(&p23));
        }
    };

    const uint32_t aRow = lane & 15, aCol = (lane >> 4) * 8;
    const uint32_t bRow = (lane >> 4) * 8 + (lane & 7), bCol = ((lane >> 3) & 1) * 8;
    const uint32_t uAhi = (uint32_t)__cvta_generic_to_shared(SM_AHI);
    const uint32_t uAlo = (uint32_t)__cvta_generic_to_shared(SM_ALO);

    stage(0, 0);
    for (int c0 = 0; c0 < FIN / KC; c0++) {
        const int b = c0 & 1;
        CP_WAIT0();
        __syncthreads();
        if (c0 + 1 < FIN / KC) stage((c0 + 1) * KC, 1 - b);
        convert(b);
        __syncthreads();
        const uint32_t uBhi = (uint32_t)__cvta_generic_to_shared(SM_BHI(b));
        const uint32_t uBlo = (uint32_t)__cvta_generic_to_shared(SM_BLO(b));
#pragma unroll
        for (int ks = 0; ks < 2; ks++) {
            const uint32_t aOff = ((mbase + aRow) * LDA + ks * 16 + aCol) * 2;
            const uint32_t bOff = ((nbase + bRow) * LDA + ks * 16 + bCol) * 2;
            uint32_t ahi[4][4], alo[4][4];
            uint32_t bh[2][4], bl[2][4];
#pragma unroll
            for (int mi = 0; mi < 4; mi++) {
                ldsm4(ahi[mi], uAhi + aOff + (uint32_t)(mi * 16 * LDA * 2));
                ldsm4(alo[mi], uAlo + aOff + (uint32_t)(mi * 16 * LDA * 2));
            }
#pragma unroll
            for (int p = 0; p < 2; p++) {
                ldsm4(bh[p], uBhi + bOff + (uint32_t)(p * 16 * LDA * 2));
                ldsm4(bl[p], uBlo + bOff + (uint32_t)(p * 16 * LDA * 2));
            }
#pragma unroll
            for (int mi = 0; mi < 4; mi++)
#pragma unroll
                for (int ni = 0; ni < 4; ni++) {
                    const uint32_t* bhi_n = &bh[ni >> 1][(ni & 1) * 2];
                    const uint32_t* blo_n = &bl[ni >> 1][(ni & 1) * 2];
                    mma16816(acc[mi][ni], ahi[mi], bhi_n);
                    mma16816(acc[mi][ni], ahi[mi], blo_n);
                    mma16816(acc[mi][ni], alo[mi], bhi_n);
                }
        }
        __syncthreads();
    }
#pragma unroll
    for (int mi = 0; mi < 4; mi++) {
        int row0 = bm + mbase + mi * 16 + g;
        int row1 = row0 + 8;
#pragma unroll
        for (int ni = 0; ni < 4; ni++) {
            int col = nbase + ni * 8 + tg * 2;
            if (row0 < NN)
                *reinterpret_cast<float2*>(g_h1 + (size_t)row0 * D1 + col) =
                    make_float2(acc[mi][ni][0], acc[mi][ni][1]);
            if (row1 < NN)
                *reinterpret_cast<float2*>(g_h1 + (size_t)row1 * D1 + col) =
                    make_float2(acc[mi][ni][2], acc[mi][ni][3]);
        }
    }
    float atS[4][2], atD[4][2];
#pragma unroll
    for (int ni = 0; ni < 4; ni++) {
        int col = nbase + ni * 8 + tg * 2;
        atS[ni][0] = __ldg(att_s + col);     atS[ni][1] = __ldg(att_s + col + 1);
        atD[ni][0] = __ldg(att_d + col);     atD[ni][1] = __ldg(att_d + col + 1);
    }
    float* sPart = reinterpret_cast<float*>(sm);
#pragma unroll
    for (int mi = 0; mi < 4; mi++) {
#pragma unroll
        for (int half = 0; half < 2; half++) {
            float aS0 = 0.f, aD0 = 0.f, aS1 = 0.f, aD1 = 0.f;
#pragma unroll
            for (int ni = 0; ni < 2; ni++) {
                aS0 += acc[mi][ni][half*2] * atS[ni][0] + acc[mi][ni][half*2+1] * atS[ni][1];
                aD0 += acc[mi][ni][half*2] * atD[ni][0] + acc[mi][ni][half*2+1] * atD[ni][1];
            }
#pragma unroll
            for (int ni = 2; ni < 4; ni++) {
                aS1 += acc[mi][ni][half*2] * atS[ni][0] + acc[mi][ni][half*2+1] * atS[ni][1];
                aD1 += acc[mi][ni][half*2] * atD[ni][0] + acc[mi][ni][half*2+1] * atD[ni][1];
            }
#pragma unroll
            for (int d = 1; d < 4; d <<= 1) {
                aS0 += __shfl_xor_sync(0xffffffffu, aS0, d);
                aD0 += __shfl_xor_sync(0xffffffffu, aD0, d);
                aS1 += __shfl_xor_sync(0xffffffffu, aS1, d);
                aD1 += __shfl_xor_sync(0xffffffffu, aD1, d);
            }
            if (tg == 0) {
                int lr = mbase + mi * 16 + half * 8 + g;
                float* p = sPart + ((lr * 4 + nwarp) * 2) * 2;
                p[0] = aS0; p[1] = aD0; p[2] = aS1; p[3] = aD1;
            }
        }
    }
    __syncthreads();
    if (tid < 128) {
        int node = bm + tid;
        if (node < NN) {
#pragma unroll
            for (int nw = 0; nw < 4; nw++)
#pragma unroll
                for (int h = 0; h < 2; h++) {
                    const float* p = sPart + ((tid * 4 + nw) * 2 + h) * 2;
                    g_as1[node * H1 + nw * 2 + h] = p[0];
                    g_ad1[node * H1 + nw * 2 + h] = p[1];
                }
        }
    }
}

// ======================== CSR build by destination =========================
__global__ void k_hist(const int* __restrict__ dst) {
    int i = blockIdx.x * blockDim.x + threadIdx.x;
    if (i < EE) atomicAdd(&g_off[dst[i] + 1], 1);
}
__global__ __launch_bounds__(1024) void k_scan() {
    __shared__ int wsum[32];
    __shared__ int s_carry;
    int tid = threadIdx.x, lane = tid & 31, wid = tid >> 5;
    if (tid == 0) s_carry = 0;
    __syncthreads();
    const int n = NN + 1;
    for (int base = 0; base < n; base += 1024 * 8) {
        int v[8];
        int i0 = base + tid * 8;
#pragma unroll
        for (int i = 0; i < 8; i++) { int ii = i0 + i; v[i] = (ii < n) ? g_off[ii] : 0; }
#pragma unroll
        for (int i = 1; i < 8; i++) v[i] += v[i - 1];
        int tot = v[7];
        int t = tot;
#pragma unroll
        for (int d = 1; d < 32; d <<= 1) {
            int u = __shfl_up_sync(0xffffffffu, t, d);
            if (lane >= d) t += u;
        }
        if (lane == 31) wsum[wid] = t;
        __syncthreads();
        if (wid == 0) {
            int w = wsum[lane];
#pragma unroll
            for (int d = 1; d < 32; d <<= 1) {
                int u = __shfl_up_sync(0xffffffffu, w, d);
                if (lane >= d) w += u;
            }
            wsum[lane] = w;
        }
        __syncthreads();
        int c = s_carry;
        int add = c + (wid ? wsum[wid - 1] : 0) + (t - tot);
#pragma unroll
        for (int i = 0; i < 8; i++) {
            int ii = i0 + i;
            if (ii < n) {
                int val = v[i] + add;
                g_off[ii] = val;
                if (ii < NN) g_cur[ii] = val;
            }
        }
        __syncthreads();
        if (tid == 0) s_carry = c + wsum[31];
        __syncthreads();
    }
}
__global__ void k_scatter(const int* __restrict__ src, const int* __restrict__ dst) {
    int i = blockIdx.x * blockDim.x + threadIdx.x;
    if (i < EE) {
        int d = dst[i];
        int p = atomicAdd(&g_cur[d], 1);
        g_ssrc[p] = src[i];
    }
}

// ===== agg1 + FUSED gemm2/attn2 ============================================
// Warp/node online segment-softmax (proven loop, unchanged math) -> h1e row
// staged in smem -> k_gemm2-style LDS micro-GEMM -> h2 + as2/ad2.
__global__ __launch_bounds__(256) void k_agg1g2(const float* __restrict__ b1,
                                                const float* __restrict__ W2,
                                                const float* __restrict__ attS2,
                                                const float* __restrict__ attD2) {
    __shared__ float sW2[D1 * C2];    // 16 KB
    __shared__ float sH[8][D1];       // 4 KB
    __shared__ float sAS[C2], sAD[C2];
    const int tid = threadIdx.x;
    for (int i = tid; i < (D1 * C2) / 4; i += 256)
        reinterpret_cast<float4*>(sW2)[i] = reinterpret_cast<const float4*>(W2)[i];
    if (tid < C2) { sAS[tid] = attS2[tid]; sAD[tid] = attD2[tid]; }

    const int wip = tid >> 5, lane = tid & 31;
    const int node = blockIdx.x * 8 + wip;

    if (node < NN) {
        const int head = lane >> 2;
        const int beg = g_off[node], end = g_off[node + 1];
        const float adst = g_ad1[node * H1 + head];
        float m = -INFINITY, l = 0.f;
        float4 acc = make_float4(0.f, 0.f, 0.f, 0.f);
        for (int j = beg; j < end; ++j) {
            int s = g_ssrc[j];
            float e = g_as1[s * H1 + head] + adst;
            e = e > 0.f ? e : NEG * e;
            float nm = fmaxf(m, e);
            float sc = __expf(m - nm);
            float p  = __expf(e - nm);
            l = l * sc + p;
            float4 hv = *reinterpret_cast<const float4*>(g_h1 + (size_t)s * D1 + lane * 4);
            acc.x = acc.x * sc + p * hv.x;
            acc.y = acc.y * sc + p * hv.y;
            acc.z = acc.z * sc + p * hv.z;
            acc.w = acc.w * sc + p * hv.w;
            m = nm;
        }
        float inv = 1.f / fmaxf(l, 1e-16f);
        float4 b = *reinterpret_cast<const float4*>(b1 + lane * 4);
        float o0 = acc.x * inv + b.x; o0 = o0 > 0.f ? o0 : expm1f(o0);
        float o1 = acc.y * inv + b.y; o1 = o1 > 0.f ? o1 : expm1f(o1);
        float o2 = acc.z * inv + b.z; o2 = o2 > 0.f ? o2 : expm1f(o2);
        float o3 = acc.w * inv + b.w; o3 = o3 > 0.f ? o3 : expm1f(o3);
        *reinterpret_cast<float4*>(&sH[wip][lane * 4]) = make_float4(o0, o1, o2, o3);
    }
    __syncthreads();
    if (node < NN) {
        const float* row = sH[wip];
        float h2v = 0.f;
#pragma unroll 8
        for (int k4 = 0; k4 < 32; k4++) {
            float4 hq = *reinterpret_cast<const float4*>(row + k4 * 4);
            h2v = fmaf(hq.x, sW2[(k4 * 4 + 0) * C2 + lane], h2v);
            h2v = fmaf(hq.y, sW2[(k4 * 4 + 1) * C2 + lane], h2v);
            h2v = fmaf(hq.z, sW2[(k4 * 4 + 2) * C2 + lane], h2v);
            h2v = fmaf(hq.w, sW2[(k4 * 4 + 3) * C2 + lane], h2v);
        }
        g_h2[(size_t)node * C2 + lane] = h2v;
        float as = h2v * sAS[lane];
        float ad = h2v * sAD[lane];
#pragma unroll
        for (int d = 16; d >= 1; d >>= 1) {
            as += __shfl_xor_sync(0xffffffffu, as, d);
            ad += __shfl_xor_sync(0xffffffffu, ad, d);
        }
        if (lane == 0) { g_as2[node] = as; g_ad2[node] = ad; }
    }
}

// ===== agg2: warp/node softmax-aggregate + bias + log_softmax -> out =======
__global__ void k_agg2(const float* __restrict__ b2, float* __restrict__ out) {
    int gt = blockIdx.x * blockDim.x + threadIdx.x;
    int node = gt >> 5, lane = gt & 31;
    if (node >= NN) return;
    int beg = g_off[node], end = g_off[node + 1];
    float adst = g_ad2[node];
    float m = -INFINITY, l = 0.f, acc = 0.f;
    for (int j = beg; j < end; ++j) {
        int s = g_ssrc[j];
        float e = g_as2[s] + adst;
        e = e > 0.f ? e : NEG * e;
        float nm = fmaxf(m, e);
        float sc = __expf(m - nm);
        float p  = __expf(e - nm);
        l = l * sc + p;
        acc = acc * sc + p * g_h2[(size_t)s * C2 + lane];
        m = nm;
    }
    float v = acc * (1.f / fmaxf(l, 1e-16f)) + b2[lane];
    float mx = v;
#pragma unroll
    for (int d = 16; d >= 1; d >>= 1) mx = fmaxf(mx, __shfl_xor_sync(0xffffffffu, mx, d));
    float ex = __expf(v - mx);
    float sm = ex;
#pragma unroll
    for (int d = 16; d >= 1; d >>= 1) sm += __shfl_xor_sync(0xffffffffu, sm, d);
    out[(size_t)node * C2 + lane] = v - mx - __logf(sm);
}

// ============================== launch =====================================
extern "C" void kernel_launch(void* const* d_in, const int* in_sizes, int n_in,
                              void* d_out, int out_size) {
    const float* x   = (const float*)d_in[0];
    const float* W1  = (const float*)d_in[1];
    const float* as1 = (const float*)d_in[2];
    const float* ad1 = (const float*)d_in[3];
    const float* b1  = (const float*)d_in[4];
    const float* W2  = (const float*)d_in[5];
    const float* as2 = (const float*)d_in[6];
    const float* ad2 = (const float*)d_in[7];
    const float* b2  = (const float*)d_in[8];
    const int*   ei  = (const int*)d_in[9];
    const int*   src = ei;
    const int*   dst = ei + EE;
    float* out = (float*)d_out;

    cudaFuncSetAttribute(k_gemm1_mma, cudaFuncAttributeMaxDynamicSharedMemorySize,
                         GEMM1_SMEM);

    // 7 launches; slot-4 ncu capture = k_scan (last unmeasured unknown)
    k_pre      <<<256 + (NN + 1 + 255) / 256, 256>>>(W1);
    k_hist     <<<(EE + 255) / 256, 256>>>(dst);
    k_gemm1_mma<<<(NN + 127) / 128, 256, GEMM1_SMEM>>>(x, as1, ad1);
    k_scan     <<<1, 1024>>>();
    k_scatter  <<<(EE + 255) / 256, 256>>>(src, dst);
    k_agg1g2   <<<(NN + 7) / 8, 256>>>(b1, W2, as2, ad2);
    k_agg2     <<<(NN * 32) / 256, 256>>>(b2, out);
}

// round 17
// speedup vs baseline: 1.1979x; 1.1979x over previous
#include <cuda_runtime.h>
#include <cuda_bf16.h>
#include <cstdint>
#include <cstddef>
#include <math.h>

#define NN   50000
#define EE   800000
#define FIN  512
#define D1   128      // HEADS * FPH
#define H1   8
#define C2   32       // NUM_CLASSES
#define NEG  0.2f
#define MNEG (-3.0e38f)
#define SCAN_BLKS 196   // ceil((NN+1)/256)

// ---------------- scratch (device globals; no allocation allowed) ----------
__device__ float g_h1 [NN * D1];   // x @ W1
__device__ float g_h1e[NN * D1];   // elu(gat1 out + b1)
__device__ float g_as1[NN * H1];
__device__ float g_ad1[NN * H1];
__device__ float g_h2 [NN * C2];   // h1e @ W2
__device__ float g_as2[NN];
__device__ float g_ad2[NN];
__device__ int   g_off [NN + 1];   // CSR offsets by dst
__device__ int   g_cur [NN];       // scatter cursors
__device__ int   g_ssrc[EE];       // src ids sorted by dst segment
__device__ int   g_bsum[SCAN_BLKS];
__device__ __nv_bfloat16 g_w1t_hi[D1 * FIN];   // W1^T hi  [128 n][512 k]
__device__ __nv_bfloat16 g_w1t_lo[D1 * FIN];   // W1^T lo

// ===== pre: W1T hi/lo split (blocks 0..255) + zero offsets (blocks 256+) ===
__global__ void k_pre(const float* __restrict__ W1) {
    if (blockIdx.x < 256) {
        int i = blockIdx.x * 256 + threadIdx.x;      // FIN*D1 = 65536 exactly
        int k = i >> 7, n = i & 127;
        float w = W1[i];
        __nv_bfloat16 hi = __float2bfloat16_rn(w);
        __nv_bfloat16 lo = __float2bfloat16_rn(w - __bfloat162float(hi));
        g_w1t_hi[n * FIN + k] = hi;
        g_w1t_lo[n * FIN + k] = lo;
    } else {
        int i = (blockIdx.x - 256) * 256 + threadIdx.x;
        if (i <= NN) g_off[i] = 0;
    }
}

// ============ mma.sync + cp.async + ldmatrix helpers =======================
__device__ __forceinline__ void mma16816(float* c, const uint32_t* a, const uint32_t* b) {
    asm volatile(
        "mma.sync.aligned.m16n8k16.row.col.f32.bf16.bf16.f32 "
        "{%0,%1,%2,%3}, {%4,%5,%6,%7}, {%8,%9}, {%0,%1,%2,%3};"
        : "+f"(c[0]), "+f"(c[1]), "+f"(c[2]), "+f"(c[3])
        : "r"(a[0]), "r"(a[1]), "r"(a[2]), "r"(a[3]), "r"(b[0]), "r"(b[1]));
}
__device__ __forceinline__ void cp_async16(void* dst, const void* src, int srcbytes) {
    uint32_t d = (uint32_t)__cvta_generic_to_shared(dst);
    asm volatile("cp.async.ca.shared.global [%0], [%1], 16, %2;"
                 :: "r"(d), "l"(src), "r"(srcbytes) : "memory");
}
#define CP_COMMIT() asm volatile("cp.async.commit_group;" ::: "memory")
#define CP_WAIT0()  asm volatile("cp.async.wait_group 0;" ::: "memory")
__device__ __forceinline__ void ldsm4(uint32_t* r, uint32_t saddr) {
    asm volatile("ldmatrix.sync.aligned.m8n8.x4.shared.b16 {%0,%1,%2,%3}, [%4];"
                 : "=r"(r[0]), "=r"(r[1]), "=r"(r[2]), "=r"(r[3]) : "r"(saddr));
}

// ====== GEMM1: g_h1 = x @ W1 (bf16x3 split mma.sync) + FUSED attn1 dots ====
#define KC 32
#define LDA 40
#define LDA32 36
#define SM_A32(b)  (sm + (b) * 18432)
#define SM_BHI(b)  (sm + 36864 + (b) * 20480)
#define SM_BLO(b)  (sm + 36864 + (b) * 20480 + 10240)
#define SM_AHI     (sm + 77824)
#define SM_ALO     (sm + 88064)
#define GEMM1_SMEM 98304
__global__ __launch_bounds__(256, 2) void k_gemm1_mma(const float* __restrict__ A,
                                                      const float* __restrict__ att_s,
                                                      const float* __restrict__ att_d) {
    extern __shared__ char sm[];
    const int tid  = threadIdx.x;
    const int bm   = blockIdx.x * 128;
    const int warp = tid >> 5, lane = tid & 31;
    const int g = lane >> 2, tg = lane & 3;
    const int mwarp = warp >> 2, nwarp = warp & 3;
    const int mbase = mwarp * 64;
    const int nbase = nwarp * 32;

    float acc[4][4][4];
#pragma unroll
    for (int mi = 0; mi < 4; mi++)
#pragma unroll
        for (int ni = 0; ni < 4; ni++)
#pragma unroll
            for (int q = 0; q < 4; q++) acc[mi][ni][q] = 0.f;

    auto stage = [&](int k0, int b) {
        float* a32 = reinterpret_cast<float*>(SM_A32(b));
#pragma unroll
        for (int i = 0; i < 4; i++) {
            int idx = i * 256 + tid;
            int r = idx >> 3, q = idx & 7;
            int gr = bm + r;
            int okb = (gr < NN) ? 16 : 0;
            int gc = (gr < NN) ? gr : (NN - 1);
            cp_async16(a32 + r * LDA32 + q * 4,
                       A + (size_t)gc * FIN + k0 + q * 4, okb);
        }
        __nv_bfloat16* bhi = reinterpret_cast<__nv_bfloat16*>(SM_BHI(b));
        __nv_bfloat16* blo = reinterpret_cast<__nv_bfloat16*>(SM_BLO(b));
#pragma unroll
        for (int i = 0; i < 4; i++) {
            int idx = i * 256 + tid;
            int which = idx >> 9, wi = idx & 511;
            int r = wi >> 2, q = wi & 3;
            const __nv_bfloat16* src = (which ? g_w1t_lo : g_w1t_hi) + r * FIN + k0 + q * 8;
            __nv_bfloat16* dst = (which ? blo : bhi) + r * LDA + q * 8;
            cp_async16(dst, src, 16);
        }
        CP_COMMIT();
    };
    auto convert = [&](int b) {
        const float* a32 = reinterpret_cast<const float*>(SM_A32(b));
        __nv_bfloat16* ahi = reinterpret_cast<__nv_bfloat16*>(SM_AHI);
        __nv_bfloat16* alo = reinterpret_cast<__nv_bfloat16*>(SM_ALO);
#pragma unroll
        for (int i = 0; i < 4; i++) {
            int idx = i * 256 + tid;
            int r = idx >> 3, q = idx & 7;
            float4 v = *reinterpret_cast<const float4*>(a32 + r * LDA32 + q * 4);
            __nv_bfloat162 h01 = __floats2bfloat162_rn(v.x, v.y);
            __nv_bfloat162 h23 = __floats2bfloat162_rn(v.z, v.w);
            float l0 = v.x - __bfloat162float(h01.x);
            float l1 = v.y - __bfloat162float(h01.y);
            float l2 = v.z - __bfloat162float(h23.x);
            float l3 = v.w - __bfloat162float(h23.y);
            __nv_bfloat162 p01 = __floats2bfloat162_rn(l0, l1);
            __nv_bfloat162 p23 = __floats2bfloat162_rn(l2, l3);
            int so = r * LDA + q * 4;
            *reinterpret_cast<uint2*>(ahi + so) =
                make_uint2(*reinterpret_cast<uint32_t*>(&h01), *reinterpret_cast<uint32_t*>(&h23));
            *reinterpret_cast<uint2*>(alo + so) =
                make_uint2(*reinterpret_cast<uint32_t*>(&p01), *reinterpret_cast<uint32_t*>(&p23));
        }
    };

    const uint32_t aRow = lane & 15, aCol = (lane >> 4) * 8;
    const uint32_t bRow = (lane >> 4) * 8 + (lane & 7), bCol = ((lane >> 3) & 1) * 8;
    const uint32_t uAhi = (uint32_t)__cvta_generic_to_shared(SM_AHI);
    const uint32_t uAlo = (uint32_t)__cvta_generic_to_shared(SM_ALO);

    stage(0, 0);
    for (int c0 = 0; c0 < FIN / KC; c0++) {
        const int b = c0 & 1;
        CP_WAIT0();
        __syncthreads();
        if (c0 + 1 < FIN / KC) stage((c0 + 1) * KC, 1 - b);
        convert(b);
        __syncthreads();
        const uint32_t uBhi = (uint32_t)__cvta_generic_to_shared(SM_BHI(b));
        const uint32_t uBlo = (uint32_t)__cvta_generic_to_shared(SM_BLO(b));
#pragma unroll
        for (int ks = 0; ks < 2; ks++) {
            const uint32_t aOff = ((mbase + aRow) * LDA + ks * 16 + aCol) * 2;
            const uint32_t bOff = ((nbase + bRow) * LDA + ks * 16 + bCol) * 2;
            uint32_t ahi[4][4], alo[4][4];
            uint32_t bh[2][4], bl[2][4];
#pragma unroll
            for (int mi = 0; mi < 4; mi++) {
                ldsm4(ahi[mi], uAhi + aOff + (uint32_t)(mi * 16 * LDA * 2));
                ldsm4(alo[mi], uAlo + aOff + (uint32_t)(mi * 16 * LDA * 2));
            }
#pragma unroll
            for (int p = 0; p < 2; p++) {
                ldsm4(bh[p], uBhi + bOff + (uint32_t)(p * 16 * LDA * 2));
                ldsm4(bl[p], uBlo + bOff + (uint32_t)(p * 16 * LDA * 2));
            }
#pragma unroll
            for (int mi = 0; mi < 4; mi++)
#pragma unroll
                for (int ni = 0; ni < 4; ni++) {
                    const uint32_t* bhi_n = &bh[ni >> 1][(ni & 1) * 2];
                    const uint32_t* blo_n = &bl[ni >> 1][(ni & 1) * 2];
                    mma16816(acc[mi][ni], ahi[mi], bhi_n);
                    mma16816(acc[mi][ni], ahi[mi], blo_n);
                    mma16816(acc[mi][ni], alo[mi], bhi_n);
                }
        }
        __syncthreads();
    }
#pragma unroll
    for (int mi = 0; mi < 4; mi++) {
        int row0 = bm + mbase + mi * 16 + g;
        int row1 = row0 + 8;
#pragma unroll
        for (int ni = 0; ni < 4; ni++) {
            int col = nbase + ni * 8 + tg * 2;
            if (row0 < NN)
                *reinterpret_cast<float2*>(g_h1 + (size_t)row0 * D1 + col) =
                    make_float2(acc[mi][ni][0], acc[mi][ni][1]);
            if (row1 < NN)
                *reinterpret_cast<float2*>(g_h1 + (size_t)row1 * D1 + col) =
                    make_float2(acc[mi][ni][2], acc[mi][ni][3]);
        }
    }
    float atS[4][2], atD[4][2];
#pragma unroll
    for (int ni = 0; ni < 4; ni++) {
        int col = nbase + ni * 8 + tg * 2;
        atS[ni][0] = __ldg(att_s + col);     atS[ni][1] = __ldg(att_s + col + 1);
        atD[ni][0] = __ldg(att_d + col);     atD[ni][1] = __ldg(att_d + col + 1);
    }
    float* sPart = reinterpret_cast<float*>(sm);
#pragma unroll
    for (int mi = 0; mi < 4; mi++) {
#pragma unroll
        for (int half = 0; half < 2; half++) {
            float aS0 = 0.f, aD0 = 0.f, aS1 = 0.f, aD1 = 0.f;
#pragma unroll
            for (int ni = 0; ni < 2; ni++) {
                aS0 += acc[mi][ni][half*2] * atS[ni][0] + acc[mi][ni][half*2+1] * atS[ni][1];
                aD0 += acc[mi][ni][half*2] * atD[ni][0] + acc[mi][ni][half*2+1] * atD[ni][1];
            }
#pragma unroll
            for (int ni = 2; ni < 4; ni++) {
                aS1 += acc[mi][ni][half*2] * atS[ni][0] + acc[mi][ni][half*2+1] * atS[ni][1];
                aD1 += acc[mi][ni][half*2] * atD[ni][0] + acc[mi][ni][half*2+1] * atD[ni][1];
            }
#pragma unroll
            for (int d = 1; d < 4; d <<= 1) {
                aS0 += __shfl_xor_sync(0xffffffffu, aS0, d);
                aD0 += __shfl_xor_sync(0xffffffffu, aD0, d);
                aS1 += __shfl_xor_sync(0xffffffffu, aS1, d);
                aD1 += __shfl_xor_sync(0xffffffffu, aD1, d);
            }
            if (tg == 0) {
                int lr = mbase + mi * 16 + half * 8 + g;
                float* p = sPart + ((lr * 4 + nwarp) * 2) * 2;
                p[0] = aS0; p[1] = aD0; p[2] = aS1; p[3] = aD1;
            }
        }
    }
    __syncthreads();
    if (tid < 128) {
        int node = bm + tid;
        if (node < NN) {
#pragma unroll
            for (int nw = 0; nw < 4; nw++)
#pragma unroll
                for (int h = 0; h < 2; h++) {
                    const float* p = sPart + ((tid * 4 + nw) * 2 + h) * 2;
                    g_as1[node * H1 + nw * 2 + h] = p[0];
                    g_ad1[node * H1 + nw * 2 + h] = p[1];
                }
        }
    }
}

// ======================== CSR build by destination =========================
__global__ void k_hist(const int* __restrict__ dst) {
    int i = blockIdx.x * blockDim.x + threadIdx.x;
    if (i < EE) atomicAdd(&g_off[dst[i] + 1], 1);
}

// scan phase 1: per-block (256 elems) inclusive scan + block sums
__global__ __launch_bounds__(256) void k_scan1() {
    __shared__ int ws[8];
    const int b = blockIdx.x, tid = threadIdx.x;
    const int lane = tid & 31, wid = tid >> 5;
    const int i = b * 256 + tid;
    int v = (i <= NN) ? g_off[i] : 0;
    int t = v;
#pragma unroll
    for (int d = 1; d < 32; d <<= 1) {
        int u = __shfl_up_sync(0xffffffffu, t, d);
        if (lane >= d) t += u;
    }
    if (lane == 31) ws[wid] = t;
    __syncthreads();
    if (wid == 0 && lane < 8) {
        int w = ws[lane];
#pragma unroll
        for (int d = 1; d < 8; d <<= 1) {
            int u = __shfl_up_sync(0xffu, w, d);
            if (lane >= d) w += u;
        }
        ws[lane] = w;
    }
    __syncthreads();
    int res = t + (wid ? ws[wid - 1] : 0);
    if (i <= NN) g_off[i] = res;
    if (tid == 255) g_bsum[b] = res;
}

// scan phase 2: scan block sums, add offsets, seed g_cur
__global__ __launch_bounds__(1024) void k_scan2() {
    __shared__ int s[SCAN_BLKS];
    const int tid = threadIdx.x;
    if (tid < SCAN_BLKS) s[tid] = g_bsum[tid];
    __syncthreads();
    for (int d = 1; d < SCAN_BLKS; d <<= 1) {
        int v = 0;
        if (tid < SCAN_BLKS && tid >= d) v = s[tid - d];
        __syncthreads();
        if (tid < SCAN_BLKS && tid >= d) s[tid] += v;
        __syncthreads();
    }
    for (int i = tid; i <= NN; i += 1024) {
        int b = i >> 8;
        int val = g_off[i] + (b ? s[b - 1] : 0);
        g_off[i] = val;
        if (i < NN) g_cur[i] = val;
    }
}

__global__ void k_scatter(const int* __restrict__ src, const int* __restrict__ dst) {
    int i = blockIdx.x * blockDim.x + threadIdx.x;
    if (i < EE) {
        int d = dst[i];
        int p = atomicAdd(&g_cur[d], 1);
        g_ssrc[p] = src[i];
    }
}

// ===== agg1: warp/node online segment-softmax + aggregate + bias + ELU =====
__global__ void k_agg1(const float* __restrict__ b1) {
    int gt = blockIdx.x * blockDim.x + threadIdx.x;
    int node = gt >> 5, lane = gt & 31;
    if (node >= NN) return;
    int head = lane >> 2;
    int beg = g_off[node], end = g_off[node + 1];
    float adst = g_ad1[node * H1 + head];
    float m = -INFINITY, l = 0.f;
    float4 acc = make_float4(0.f, 0.f, 0.f, 0.f);
    for (int j = beg; j < end; ++j) {
        int s = g_ssrc[j];
        float e = g_as1[s * H1 + head] + adst;
        e = e > 0.f ? e : NEG * e;
        float nm = fmaxf(m, e);
        float sc = __expf(m - nm);
        float p  = __expf(e - nm);
        l = l * sc + p;
        float4 hv = *reinterpret_cast<const float4*>(g_h1 + (size_t)s * D1 + lane * 4);
        acc.x = acc.x * sc + p * hv.x;
        acc.y = acc.y * sc + p * hv.y;
        acc.z = acc.z * sc + p * hv.z;
        acc.w = acc.w * sc + p * hv.w;
        m = nm;
    }
    float inv = 1.f / fmaxf(l, 1e-16f);
    float4 b = *reinterpret_cast<const float4*>(b1 + lane * 4);
    float o0 = acc.x * inv + b.x; o0 = o0 > 0.f ? o0 : expm1f(o0);
    float o1 = acc.y * inv + b.y; o1 = o1 > 0.f ? o1 : expm1f(o1);
    float o2 = acc.z * inv + b.z; o2 = o2 > 0.f ? o2 : expm1f(o2);
    float o3 = acc.w * inv + b.w; o3 = o3 > 0.f ? o3 : expm1f(o3);
    *reinterpret_cast<float4*>(g_h1e + (size_t)node * D1 + lane * 4) =
        make_float4(o0, o1, o2, o3);
}

// ===== GEMM2 + attn2: h2 = h1e @ W2 ; a_src2/a_dst2 ========================
__global__ __launch_bounds__(256) void k_gemm2(const float* __restrict__ W2,
                                               const float* __restrict__ attS,
                                               const float* __restrict__ attD) {
    __shared__ float sW[D1 * C2];
    __shared__ float sR[32][132];
    __shared__ float sAS[C2], sAD[C2];
    int tid = threadIdx.x;
    for (int i = tid; i < (D1 * C2) / 4; i += 256)
        reinterpret_cast<float4*>(sW)[i] = reinterpret_cast<const float4*>(W2)[i];
    if (tid < C2) { sAS[tid] = attS[tid]; sAD[tid] = attD[tid]; }
    int n0 = blockIdx.x * 32;
    for (int i = tid; i < 32 * 32; i += 256) {
        int r = i >> 5, c4 = i & 31;
        int node = n0 + r;
        float4 v = make_float4(0.f, 0.f, 0.f, 0.f);
        if (node < NN)
            v = *reinterpret_cast<const float4*>(g_h1e + (size_t)node * D1 + c4 * 4);
        *reinterpret_cast<float4*>(&sR[r][c4 * 4]) = v;
    }
    __syncthreads();
    int w = tid >> 5, lane = tid & 31;
    int rr = lane >> 3, c0 = lane & 7;
    int node = n0 + w * 4 + rr;
    const float* row = sR[w * 4 + rr];
    float4 v = make_float4(0.f, 0.f, 0.f, 0.f);
#pragma unroll 16
    for (int k = 0; k < D1; k++) {
        float hk = row[k];
        float4 wv = *reinterpret_cast<const float4*>(&sW[k * C2 + c0 * 4]);
        v.x = fmaf(hk, wv.x, v.x);
        v.y = fmaf(hk, wv.y, v.y);
        v.z = fmaf(hk, wv.z, v.z);
        v.w = fmaf(hk, wv.w, v.w);
    }
    float as = 0.f, ad = 0.f;
    if (node < NN) {
        *reinterpret_cast<float4*>(g_h2 + (size_t)node * C2 + c0 * 4) = v;
        as = v.x * sAS[c0 * 4] + v.y * sAS[c0 * 4 + 1] + v.z * sAS[c0 * 4 + 2] + v.w * sAS[c0 * 4 + 3];
        ad = v.x * sAD[c0 * 4] + v.y * sAD[c0 * 4 + 1] + v.z * sAD[c0 * 4 + 2] + v.w * sAD[c0 * 4 + 3];
    }
#pragma unroll
    for (int d = 1; d < 8; d <<= 1) {
        as += __shfl_xor_sync(0xffffffffu, as, d);
        ad += __shfl_xor_sync(0xffffffffu, ad, d);
    }
    if (node < NN && c0 == 0) { g_as2[node] = as; g_ad2[node] = ad; }
}

// ===== agg2: warp/node softmax-aggregate + bias + log_softmax -> out =======
__global__ void k_agg2(const float* __restrict__ b2, float* __restrict__ out) {
    int gt = blockIdx.x * blockDim.x + threadIdx.x;
    int node = gt >> 5, lane = gt & 31;
    if (node >= NN) return;
    int beg = g_off[node], end = g_off[node + 1];
    float adst = g_ad2[node];
    float m = -INFINITY, l = 0.f, acc = 0.f;
    for (int j = beg; j < end; ++j) {
        int s = g_ssrc[j];
        float e = g_as2[s] + adst;
        e = e > 0.f ? e : NEG * e;
        float nm = fmaxf(m, e);
        float sc = __expf(m - nm);
        float p  = __expf(e - nm);
        l = l * sc + p;
        acc = acc * sc + p * g_h2[(size_t)s * C2 + lane];
        m = nm;
    }
    float v = acc * (1.f / fmaxf(l, 1e-16f)) + b2[lane];
    float mx = v;
#pragma unroll
    for (int d = 16; d >= 1; d >>= 1) mx = fmaxf(mx, __shfl_xor_sync(0xffffffffu, mx, d));
    float ex = __expf(v - mx);
    float sm = ex;
#pragma unroll
    for (int d = 16; d >= 1; d >>= 1) sm += __shfl_xor_sync(0xffffffffu, sm, d);
    out[(size_t)node * C2 + lane] = v - mx - __logf(sm);
}

// ============================== launch =====================================
extern "C" void kernel_launch(void* const* d_in, const int* in_sizes, int n_in,
                              void* d_out, int out_size) {
    const float* x   = (const float*)d_in[0];
    const float* W1  = (const float*)d_in[1];
    const float* as1 = (const float*)d_in[2];
    const float* ad1 = (const float*)d_in[3];
    const float* b1  = (const float*)d_in[4];
    const float* W2  = (const float*)d_in[5];
    const float* as2 = (const float*)d_in[6];
    const float* ad2 = (const float*)d_in[7];
    const float* b2  = (const float*)d_in[8];
    const int*   ei  = (const int*)d_in[9];
    const int*   src = ei;
    const int*   dst = ei + EE;
    float* out = (float*)d_out;

    cudaFuncSetAttribute(k_gemm1_mma, cudaFuncAttributeMaxDynamicSharedMemorySize,
                         GEMM1_SMEM);

    // slot-4 capture = k_scan1 (verify the scan fix directly)
    k_pre      <<<256 + (NN + 1 + 255) / 256, 256>>>(W1);
    k_hist     <<<(EE + 255) / 256, 256>>>(dst);
    k_gemm1_mma<<<(NN + 127) / 128, 256, GEMM1_SMEM>>>(x, as1, ad1);
    k_scan1    <<<SCAN_BLKS, 256>>>();
    k_scan2    <<<1, 1024>>>();
    k_scatter  <<<(EE + 255) / 256, 256>>>(src, dst);
    k_agg1     <<<(NN * 32) / 256, 256>>>(b1);
    k_gemm2    <<<(NN + 31) / 32, 256>>>(W2, as2, ad2);
    k_agg2     <<<(NN * 32) / 256, 256>>>(b2, out);
}